// round 16
// baseline (speedup 1.0000x reference)
#include <cuda_runtime.h>

// Net_multi_11390253269716: 3-level GCN U-Net, 784x480 grid, C=32.
// R14: R13 base + linearity split of up-path gemms:
//   (relu(B)+up(relu(C)))@W = relu(B)@W [precomputed in gather shadows]
//                           + up(relu(C)@W) [tiny, on path]
//   Split-gathers read YA[s] + YC[parent(s)] per edge. Removes gemm_upadd0/1
//   (~34us) from the critical path.

#define NXg 784
#define NYg 480
#define C 32
#define N0 (NXg * NYg)        // 376320
#define N1 (N0 / 4)           // 94080
#define N2 (N0 / 16)          // 23520
#define E0 (4 * N0)
#define E1 (4 * N1)
#define E2 (4 * N2)
#define E12 (E1 + E2)
#define ETOT (E0 + E1 + E2)   // 1975680
#define M (N0 + N1 + N2)      // 493920
#define M12 (N1 + N2)         // 117600
#define GB1 N0
#define GB2 (N0 + N1)
#define NBLK0 ((N0 + 1023) / 1024)    // 368
#define NBLK12 ((M12 + 1023) / 1024)  // 115
#define NPB 128               // nodes per gemm block

typedef unsigned long long ull;

// ---------------- scratch ----------------
__device__ float4 g_Y  [N0 * 8];
__device__ float4 g_H  [N0 * 8];
__device__ float4 g_G2 [N1 * 8];
__device__ float4 g_G4 [N1 * 8];
__device__ float4 g_G3 [N2 * 8];
__device__ float4 g_YH [N0 * 8];   // relu(H)@w5 (side stream)
__device__ float4 g_YG [N1 * 8];   // relu(G2)@w4 (side stream)
__device__ float4 g_YC3[N2 * 8];   // relu(G3)@w4
__device__ float4 g_YC5[N1 * 8];   // relu(G4)@w5
__device__ int   g_cnt[M];
__device__ int   g_rowptr[M + 1];
__device__ int   g_eix[ETOT];
__device__ float g_dinv[M];
__device__ int   g_bsum0[NBLK0];
__device__ int   g_bsum12[NBLK12];

// ---------------- f32x2 helpers ----------------
__device__ __forceinline__ ull pk2(float a, float b) {
    ull r; asm("mov.b64 %0, {%1, %2};" : "=l"(r) : "f"(a), "f"(b)); return r;
}
__device__ __forceinline__ ull fma2_(ull a, ull b, ull c) {
    ull d; asm("fma.rn.f32x2 %0, %1, %2, %3;" : "=l"(d) : "l"(a), "l"(b), "l"(c)); return d;
}
__device__ __forceinline__ ull add2_(ull a, ull b) {
    ull d; asm("add.rn.f32x2 %0, %1, %2;" : "=l"(d) : "l"(a), "l"(b)); return d;
}
__device__ __forceinline__ float2 up2_(ull v) {
    float2 f; asm("mov.b64 {%0, %1}, %2;" : "=f"(f.x), "=f"(f.y) : "l"(v)); return f;
}
__device__ __forceinline__ float4 relu4(float4 v) {
    v.x = fmaxf(v.x, 0.f); v.y = fmaxf(v.y, 0.f);
    v.z = fmaxf(v.z, 0.f); v.w = fmaxf(v.w, 0.f);
    return v;
}

// ---------------- CSR build (split by level, R13 verbatim) ----------------
__global__ void zero_cnt() {
    int i = blockIdx.x * blockDim.x + threadIdx.x;
    if (i < M) g_cnt[i] = 0;
}

__global__ void hist0(const int* __restrict__ d0) {
    int t = blockIdx.x * blockDim.x + threadIdx.x;
    if (t < E0) atomicAdd(&g_cnt[d0[t]], 1);
}

__global__ void hist12(const int* __restrict__ d1, const int* __restrict__ d2) {
    int t = blockIdx.x * blockDim.x + threadIdx.x;
    if (t < E1) atomicAdd(&g_cnt[GB1 + d1[t]], 1);
    else if (t < E12) atomicAdd(&g_cnt[GB2 + d2[t - E1]], 1);
}

__global__ void scanA_r(int* bsum, int start, int nn) {
    __shared__ int sb[256];
    int tid = threadIdx.x;
    int base = blockIdx.x * 1024 + tid * 4;
    int v = 0;
    #pragma unroll
    for (int k = 0; k < 4; k++)
        if (base + k < nn) v += g_cnt[start + base + k];
    sb[tid] = v; __syncthreads();
    for (int off = 128; off; off >>= 1) {
        if (tid < off) sb[tid] += sb[tid + off];
        __syncthreads();
    }
    if (tid == 0) bsum[blockIdx.x] = sb[0];
}

__global__ void scanC2_r(const int* __restrict__ bsum, int start, int nn,
                         int rp_base, int rp_end) {
    __shared__ int sb[256];
    __shared__ int s_pre;
    int tid = threadIdx.x;
    int partial = 0;
    for (int j = tid; j < blockIdx.x; j += 256) partial += bsum[j];
    sb[tid] = partial; __syncthreads();
    for (int off = 128; off; off >>= 1) {
        if (tid < off) sb[tid] += sb[tid + off];
        __syncthreads();
    }
    if (tid == 0) s_pre = sb[0];
    __syncthreads();

    int base = blockIdx.x * 1024 + tid * 4;
    int v[4], p[4], tsum = 0;
    #pragma unroll
    for (int k = 0; k < 4; k++) {
        v[k] = (base + k < nn) ? g_cnt[start + base + k] : 0;
        p[k] = tsum; tsum += v[k];
    }
    sb[tid] = tsum; __syncthreads();
    for (int off = 1; off < 256; off <<= 1) {
        int t = (tid >= off) ? sb[tid - off] : 0;
        __syncthreads();
        sb[tid] += t;
        __syncthreads();
    }
    int off0 = rp_base + s_pre + sb[tid] - tsum;
    #pragma unroll
    for (int k = 0; k < 4; k++) {
        int i = base + k;
        if (i < nn) {
            g_rowptr[start + i] = off0 + p[k];
            g_dinv[start + i] = rsqrtf((float)v[k] + 1.0f);
            g_cnt[start + i] = 0;
        }
    }
    if (blockIdx.x == 0 && tid == 0) g_rowptr[start + nn] = rp_end;
}

__global__ void fill0(const int* __restrict__ ei0) {
    int t = blockIdx.x * blockDim.x + threadIdx.x;
    if (t >= E0) return;
    int g = ei0[E0 + t];
    int pos = g_rowptr[g] + atomicAdd(&g_cnt[g], 1);
    g_eix[pos] = ei0[t];
}

__global__ void fill12(const int* __restrict__ ei1, const int* __restrict__ ei2) {
    int t = blockIdx.x * blockDim.x + threadIdx.x;
    int g, s;
    if (t < E1)       { g = GB1 + ei1[E1 + t];              s = ei1[t]; }
    else if (t < E12) { int e = t - E1; g = GB2 + ei2[E2 + e]; s = ei2[e]; }
    else return;
    int pos = g_rowptr[g] + atomicAdd(&g_cnt[g], 1);
    g_eix[pos] = s;
}

// ---------------- staged-x gemm ----------------
#define GEMM_COMPUTE(n_, Yo_)                                             \
    __syncthreads();                                                      \
    int lane = tid & 31;                                                  \
    int sub = lane & 7, grp = lane >> 3;                                  \
    int lbase = (tid >> 5) * 16 + grp;                                    \
    ull a01[4] = {0, 0, 0, 0}, a23[4] = {0, 0, 0, 0};                     \
    _Pragma("unroll")                                                     \
    for (int g = 0; g < 8; g++) {                                         \
        ulonglong2 w0 = swu[(4 * g + 0) * 8 + sub];                       \
        ulonglong2 w1 = swu[(4 * g + 1) * 8 + sub];                       \
        ulonglong2 w2 = swu[(4 * g + 2) * 8 + sub];                       \
        ulonglong2 w3 = swu[(4 * g + 3) * 8 + sub];                       \
        _Pragma("unroll")                                                 \
        for (int j = 0; j < 4; j++) {                                     \
            float4 xv = sx[(lbase + 4 * j) * 9 + g];                      \
            a01[j] = fma2_(pk2(xv.x, xv.x), w0.x, a01[j]);                \
            a23[j] = fma2_(pk2(xv.x, xv.x), w0.y, a23[j]);                \
            a01[j] = fma2_(pk2(xv.y, xv.y), w1.x, a01[j]);                \
            a23[j] = fma2_(pk2(xv.y, xv.y), w1.y, a23[j]);                \
            a01[j] = fma2_(pk2(xv.z, xv.z), w2.x, a01[j]);                \
            a23[j] = fma2_(pk2(xv.z, xv.z), w2.y, a23[j]);                \
            a01[j] = fma2_(pk2(xv.w, xv.w), w3.x, a01[j]);                \
            a23[j] = fma2_(pk2(xv.w, xv.w), w3.y, a23[j]);                \
        }                                                                 \
    }                                                                     \
    _Pragma("unroll")                                                     \
    for (int j = 0; j < 4; j++) {                                         \
        int node = blockIdx.x * NPB + lbase + 4 * j;                      \
        if (node < n_) {                                                  \
            ulonglong2 r; r.x = a01[j]; r.y = a23[j];                     \
            ((ulonglong2*)(Yo_))[node * 8 + sub] = r;                     \
        }                                                                 \
    }

__global__ void __launch_bounds__(256)
gemm_fc1(const float4* __restrict__ x,
         const float* __restrict__ fc1w, const float* __restrict__ fc1b,
         const float* __restrict__ w, float4* __restrict__ Y, int n)
{
    __shared__ ulonglong2 swu[256];
    __shared__ float4 sx[NPB * 9];
    __shared__ float4 sfw[32];
    __shared__ float4 sfb[8];
    int tid = threadIdx.x;
    swu[tid] = ((const ulonglong2*)w)[tid];
    if (tid < 32) sfw[tid] = ((const float4*)fc1w)[tid];
    if (tid < 8)  sfb[tid] = ((const float4*)fc1b)[tid];
    __syncthreads();
    int ln = tid >> 1;
    int nd = blockIdx.x * NPB + ln;
    int half = (tid & 1) * 4;
    if (nd < n) {
        float4 xin = x[nd];
        #pragma unroll
        for (int i = 0; i < 4; i++) {
            int q = half + i;
            float4 h = sfb[q];
            float4 r0 = sfw[q], r1 = sfw[8 + q], r2 = sfw[16 + q], r3 = sfw[24 + q];
            h.x += xin.x * r0.x + xin.y * r1.x + xin.z * r2.x + xin.w * r3.x;
            h.y += xin.x * r0.y + xin.y * r1.y + xin.z * r2.y + xin.w * r3.y;
            h.z += xin.x * r0.z + xin.y * r1.z + xin.z * r2.z + xin.w * r3.z;
            h.w += xin.x * r0.w + xin.y * r1.w + xin.z * r2.w + xin.w * r3.w;
            sx[ln * 9 + q] = relu4(h);
        }
    }
    GEMM_COMPUTE(n, Y)
}

__global__ void __launch_bounds__(256)
gemm_down(const float4* __restrict__ in, const float* __restrict__ w,
          float4* __restrict__ Y, int n, int hy, int win)
{
    __shared__ ulonglong2 swu[256];
    __shared__ float4 sx[NPB * 9];
    int tid = threadIdx.x;
    swu[tid] = ((const ulonglong2*)w)[tid];
    int ln = tid >> 1;
    int nd = blockIdx.x * NPB + ln;
    int half = (tid & 1) * 4;
    if (nd < n) {
        int ix = nd / hy, iy = nd - ix * hy;
        const float4* src = in + ((2 * ix) * win + 2 * iy) * 8 + half;
        #pragma unroll
        for (int i = 0; i < 4; i++)
            sx[ln * 9 + half + i] = relu4(src[i]);
    }
    GEMM_COMPUTE(n, Y)
}

// Y = relu(X)@w (plain, node-aligned)
__global__ void __launch_bounds__(256)
gemm_plain(const float4* __restrict__ in, const float* __restrict__ w,
           float4* __restrict__ Yo, int n)
{
    __shared__ ulonglong2 swu[256];
    __shared__ float4 sx[NPB * 9];
    int tid = threadIdx.x;
    swu[tid] = ((const ulonglong2*)w)[tid];
    int ln = tid >> 1;
    int nd = blockIdx.x * NPB + ln;
    int half = (tid & 1) * 4;
    if (nd < n) {
        const float4* src = in + nd * 8 + half;
        #pragma unroll
        for (int i = 0; i < 4; i++)
            sx[ln * 9 + half + i] = relu4(src[i]);
    }
    GEMM_COMPUTE(n, Yo)
}

// ---------------- gathers ----------------
__device__ __forceinline__ void gather_acc(
    const ulonglong2* __restrict__ Y, int node, int sub, int gbase,
    const float* __restrict__ bias, ull& a01, ull& a23)
{
    float di = g_dinv[gbase + node];
    int beg = g_rowptr[gbase + node];
    int end = g_rowptr[gbase + node + 1];
    float4 bb = ((const float4*)bias)[sub];
    float s2 = di * di;
    ulonglong2 y = Y[node * 8 + sub];
    ull s22 = pk2(s2, s2);
    a01 = fma2_(y.x, s22, pk2(bb.x, bb.y));
    a23 = fma2_(y.y, s22, pk2(bb.z, bb.w));
    for (int p = beg; p < end; p++) {
        int s = g_eix[p];
        float nm = g_dinv[gbase + s] * di;
        ulonglong2 v = Y[s * 8 + sub];
        ull nn = pk2(nm, nm);
        a01 = fma2_(v.x, nn, a01);
        a23 = fma2_(v.y, nn, a23);
    }
}

// Split variant: operand row s is A[s] + Cc[parent(s)] (HY = fine grid cols).
template<int HY>
__device__ __forceinline__ void gather_acc_split(
    const ulonglong2* __restrict__ A, const ulonglong2* __restrict__ Cc,
    int node, int sub, int gbase,
    const float* __restrict__ bias, ull& a01, ull& a23)
{
    float di = g_dinv[gbase + node];
    int beg = g_rowptr[gbase + node];
    int end = g_rowptr[gbase + node + 1];
    float4 bb = ((const float4*)bias)[sub];
    int ixn = node / HY, iyn = node - ixn * HY;
    int cnn = (ixn >> 1) * (HY / 2) + (iyn >> 1);
    ulonglong2 ya = A[node * 8 + sub];
    ulonglong2 yc = Cc[cnn * 8 + sub];
    ull y01 = add2_(ya.x, yc.x), y23 = add2_(ya.y, yc.y);
    float s2 = di * di;
    ull s22 = pk2(s2, s2);
    a01 = fma2_(y01, s22, pk2(bb.x, bb.y));
    a23 = fma2_(y23, s22, pk2(bb.z, bb.w));
    for (int p = beg; p < end; p++) {
        int s = g_eix[p];
        float nm = g_dinv[gbase + s] * di;
        int ix = s / HY, iy = s - ix * HY;
        int cn = (ix >> 1) * (HY / 2) + (iy >> 1);
        ulonglong2 va = A[s * 8 + sub];
        ulonglong2 vc = Cc[cn * 8 + sub];
        ull nn = pk2(nm, nm);
        a01 = fma2_(add2_(va.x, vc.x), nn, a01);
        a23 = fma2_(add2_(va.y, vc.y), nn, a23);
    }
}

__global__ void gather(const float4* __restrict__ Yf,
                       const float* __restrict__ bias,
                       float4* __restrict__ OUT, int n, int gbase)
{
    int t = blockIdx.x * blockDim.x + threadIdx.x;
    int node = t >> 3, sub = t & 7;
    if (node >= n) return;
    ull a01, a23;
    gather_acc((const ulonglong2*)Yf, node, sub, gbase, bias, a01, a23);
    ulonglong2 r; r.x = a01; r.y = a23;
    ((ulonglong2*)OUT)[node * 8 + sub] = r;
}

template<int HY>
__global__ void gather_split(const float4* __restrict__ A,
                             const float4* __restrict__ Cc,
                             const float* __restrict__ bias,
                             float4* __restrict__ OUT, int n, int gbase)
{
    int t = blockIdx.x * blockDim.x + threadIdx.x;
    int node = t >> 3, sub = t & 7;
    if (node >= n) return;
    ull a01, a23;
    gather_acc_split<HY>((const ulonglong2*)A, (const ulonglong2*)Cc,
                         node, sub, gbase, bias, a01, a23);
    ulonglong2 r; r.x = a01; r.y = a23;
    ((ulonglong2*)OUT)[node * 8 + sub] = r;
}

template<int HY>
__global__ void gather_fc2_split(const float4* __restrict__ A,
                                 const float4* __restrict__ Cc,
                                 const float* __restrict__ bias,
                                 const float* __restrict__ w2,
                                 const float* __restrict__ b2,
                                 float* __restrict__ out, int n)
{
    __shared__ float sw[96];
    int tid = threadIdx.x;
    if (tid < 96) sw[tid] = w2[tid];
    __syncthreads();
    int t = blockIdx.x * blockDim.x + tid;
    int node = t >> 3, sub = t & 7;
    if (node >= n) return;
    ull a01, a23;
    gather_acc_split<HY>((const ulonglong2*)A, (const ulonglong2*)Cc,
                         node, sub, 0, bias, a01, a23);
    float2 v01 = up2_(a01), v23 = up2_(a23);
    float4 v = relu4(make_float4(v01.x, v01.y, v23.x, v23.y));
    int c = 4 * sub;
    float p0 = v.x * sw[(c+0)*3+0] + v.y * sw[(c+1)*3+0] + v.z * sw[(c+2)*3+0] + v.w * sw[(c+3)*3+0];
    float p1 = v.x * sw[(c+0)*3+1] + v.y * sw[(c+1)*3+1] + v.z * sw[(c+2)*3+1] + v.w * sw[(c+3)*3+1];
    float p2 = v.x * sw[(c+0)*3+2] + v.y * sw[(c+1)*3+2] + v.z * sw[(c+2)*3+2] + v.w * sw[(c+3)*3+2];
    #pragma unroll
    for (int off = 4; off; off >>= 1) {
        p0 += __shfl_down_sync(0xffffffffu, p0, off, 8);
        p1 += __shfl_down_sync(0xffffffffu, p1, off, 8);
        p2 += __shfl_down_sync(0xffffffffu, p2, off, 8);
    }
    if (sub == 0) {
        out[node * 3 + 0] = p0 + __ldg(&b2[0]);
        out[node * 3 + 1] = p1 + __ldg(&b2[1]);
        out[node * 3 + 2] = p2 + __ldg(&b2[2]);
    }
}

// ---------------------------------------------------------------------------
static inline int ceil_div(int a, int b) { return (a + b - 1) / b; }

static cudaStream_t g_s2 = 0, g_s3 = 0;
static cudaEvent_t g_evTop = 0, g_evZ = 0, g_evF = 0, g_ev12 = 0,
                   g_evG1 = 0, g_evG2 = 0, g_evYH = 0, g_evYG = 0;

extern "C" void kernel_launch(void* const* d_in, const int* in_sizes, int n_in,
                              void* d_out, int out_size) {
    const float* x     = (const float*)d_in[0];
    const float* fc1_w = (const float*)d_in[1];
    const float* fc1_b = (const float*)d_in[2];
    const float* w1 = (const float*)d_in[3];  const float* b1 = (const float*)d_in[4];
    const float* w2 = (const float*)d_in[5];  const float* b2 = (const float*)d_in[6];
    const float* w3 = (const float*)d_in[7];  const float* b3 = (const float*)d_in[8];
    const float* w4 = (const float*)d_in[9];  const float* b4 = (const float*)d_in[10];
    const float* w5 = (const float*)d_in[11]; const float* b5 = (const float*)d_in[12];
    const float* fc2_w = (const float*)d_in[13];
    const float* fc2_b = (const float*)d_in[14];
    const int* ei0 = (const int*)d_in[18];
    const int* ei1 = (const int*)d_in[19];
    const int* ei2 = (const int*)d_in[20];
    float* out = (float*)d_out;

    float4 *Y, *H, *G2, *G4, *G3, *YH, *YG, *YC3, *YC5;
    int *bs0, *bs12;
    cudaGetSymbolAddress((void**)&Y,   g_Y);
    cudaGetSymbolAddress((void**)&H,   g_H);
    cudaGetSymbolAddress((void**)&G2,  g_G2);
    cudaGetSymbolAddress((void**)&G4,  g_G4);
    cudaGetSymbolAddress((void**)&G3,  g_G3);
    cudaGetSymbolAddress((void**)&YH,  g_YH);
    cudaGetSymbolAddress((void**)&YG,  g_YG);
    cudaGetSymbolAddress((void**)&YC3, g_YC3);
    cudaGetSymbolAddress((void**)&YC5, g_YC5);
    cudaGetSymbolAddress((void**)&bs0, g_bsum0);
    cudaGetSymbolAddress((void**)&bs12, g_bsum12);

    if (!g_s2) {
        cudaStreamCreateWithFlags(&g_s2, cudaStreamNonBlocking);
        cudaStreamCreateWithFlags(&g_s3, cudaStreamNonBlocking);
        cudaEventCreateWithFlags(&g_evTop, cudaEventDisableTiming);
        cudaEventCreateWithFlags(&g_evZ,  cudaEventDisableTiming);
        cudaEventCreateWithFlags(&g_evF,  cudaEventDisableTiming);
        cudaEventCreateWithFlags(&g_ev12, cudaEventDisableTiming);
        cudaEventCreateWithFlags(&g_evG1, cudaEventDisableTiming);
        cudaEventCreateWithFlags(&g_evG2, cudaEventDisableTiming);
        cudaEventCreateWithFlags(&g_evYH, cudaEventDisableTiming);
        cudaEventCreateWithFlags(&g_evYG, cudaEventDisableTiming);
    }

    const int TB = 256;

    // Fork side streams from the capture stream.
    cudaEventRecord(g_evTop, 0);
    cudaStreamWaitEvent(g_s2, g_evTop, 0);
    cudaStreamWaitEvent(g_s3, g_evTop, 0);

    // main: zero counters + level-0 CSR
    zero_cnt<<<ceil_div(M, TB), TB>>>();
    cudaEventRecord(g_evZ, 0);
    hist0<<<ceil_div(E0, TB), TB>>>(ei0 + E0);
    scanA_r<<<NBLK0, 256>>>(bs0, 0, N0);
    scanC2_r<<<NBLK0, 256>>>(bs0, 0, N0, 0, E0);
    fill0<<<ceil_div(E0, TB), TB>>>(ei0);

    // side s2: gemm_fc1, then level-1/2 CSR
    gemm_fc1<<<ceil_div(N0, NPB), TB, 0, g_s2>>>((const float4*)x, fc1_w, fc1_b,
                                                 w1, Y, N0);
    cudaEventRecord(g_evF, g_s2);
    cudaStreamWaitEvent(g_s2, g_evZ, 0);
    hist12<<<ceil_div(E12, TB), TB, 0, g_s2>>>(ei1 + E1, ei2 + E2);
    scanA_r<<<NBLK12, 256, 0, g_s2>>>(bs12, N0, M12);
    scanC2_r<<<NBLK12, 256, 0, g_s2>>>(bs12, N0, M12, E0, ETOT);
    fill12<<<ceil_div(E12, TB), TB, 0, g_s2>>>(ei1, ei2);
    cudaEventRecord(g_ev12, g_s2);

    // main: gather1 (needs fill0 + gemm_fc1)
    cudaStreamWaitEvent(0, g_evF, 0);
    gather<<<N0 / 32, TB>>>(Y, b1, H, N0, 0);
    cudaEventRecord(g_evG1, 0);

    // side s2: YH = relu(H)@w5, hidden under GCN2-4
    cudaStreamWaitEvent(g_s2, g_evG1, 0);
    gemm_plain<<<ceil_div(N0, NPB), TB, 0, g_s2>>>(H, w5, YH, N0);
    cudaEventRecord(g_evYH, g_s2);

    // main: GCN2
    gemm_down<<<ceil_div(N1, NPB), TB>>>(H, w2, Y, N1, NYg / 2, NYg);
    cudaStreamWaitEvent(0, g_ev12, 0);
    gather<<<N1 / 32, TB>>>(Y, b2, G2, N1, GB1);
    cudaEventRecord(g_evG2, 0);

    // side s3: YG = relu(G2)@w4, hidden under GCN3
    cudaStreamWaitEvent(g_s3, g_evG2, 0);
    gemm_plain<<<ceil_div(N1, NPB), TB, 0, g_s3>>>(G2, w4, YG, N1);
    cudaEventRecord(g_evYG, g_s3);

    // main: GCN3
    gemm_down<<<ceil_div(N2, NPB), TB>>>(G2, w3, Y, N2, NYg / 4, NYg / 2);
    gather<<<N2 / 32, TB>>>(Y, b3, G3, N2, GB2);

    // main: YC3 = relu(G3)@w4 (tiny), then split gather4
    gemm_plain<<<ceil_div(N2, NPB), TB>>>(G3, w4, YC3, N2);
    cudaStreamWaitEvent(0, g_evYG, 0);
    gather_split<NYg / 2><<<N1 / 32, TB>>>(YG, YC3, b4, G4, N1, GB1);

    // main: YC5 = relu(G4)@w5 (small), then split gather5 + fc2
    gemm_plain<<<ceil_div(N1, NPB), TB>>>(G4, w5, YC5, N1);
    cudaStreamWaitEvent(0, g_evYH, 0);
    gather_fc2_split<NYg><<<N0 / 32, TB>>>(YH, YC5, b5, fc2_w, fc2_b, out, N0);

    (void)in_sizes; (void)n_in; (void)out_size;
}

// round 17
// speedup vs baseline: 1.0875x; 1.0875x over previous
#include <cuda_runtime.h>

// Net_multi_11390253269716: 3-level GCN U-Net, 784x480 grid, C=32.
// R15: R13 compute pipeline (proven) + bucket-CSR build: fixed 32-slot
//      bucket per node (one 128B line), cursor atomics, NO hist/scan.
//      Critical-path build 35us -> ~16us.

#define NXg 784
#define NYg 480
#define C 32
#define N0 (NXg * NYg)        // 376320
#define N1 (N0 / 4)           // 94080
#define N2 (N0 / 16)          // 23520
#define E0 (4 * N0)
#define E1 (4 * N1)
#define E2 (4 * N2)
#define E12 (E1 + E2)
#define M (N0 + N1 + N2)      // 493920
#define GB1 N0
#define GB2 (N0 + N1)
#define CAP 32                // bucket slots per node (P(deg>32) ~ 1e-19)
#define NPB 128               // nodes per gemm block

typedef unsigned long long ull;

// ---------------- scratch ----------------
__device__ float4 g_Y [N0 * 8];
__device__ float4 g_H [N0 * 8];
__device__ float4 g_G2[N1 * 8];
__device__ float4 g_G4[N1 * 8];
__device__ float4 g_G3[N2 * 8];
__device__ int   g_cnt[M];          // degree / bucket cursor
__device__ int   g_eix[M * CAP];    // bucket edge array (src ids)
__device__ float g_dinv[M];

// ---------------- f32x2 helpers ----------------
__device__ __forceinline__ ull pk2(float a, float b) {
    ull r; asm("mov.b64 %0, {%1, %2};" : "=l"(r) : "f"(a), "f"(b)); return r;
}
__device__ __forceinline__ ull fma2_(ull a, ull b, ull c) {
    ull d; asm("fma.rn.f32x2 %0, %1, %2, %3;" : "=l"(d) : "l"(a), "l"(b), "l"(c)); return d;
}
__device__ __forceinline__ float2 up2_(ull v) {
    float2 f; asm("mov.b64 {%0, %1}, %2;" : "=f"(f.x), "=f"(f.y) : "l"(v)); return f;
}
__device__ __forceinline__ float4 relu4(float4 v) {
    v.x = fmaxf(v.x, 0.f); v.y = fmaxf(v.y, 0.f);
    v.z = fmaxf(v.z, 0.f); v.w = fmaxf(v.w, 0.f);
    return v;
}

// ---------------- bucket-CSR build ----------------
__global__ void zero_cnt() {
    int i = blockIdx.x * blockDim.x + threadIdx.x;
    if (i < M) g_cnt[i] = 0;
}

__global__ void fill0B(const int* __restrict__ ei0) {
    int t = blockIdx.x * blockDim.x + threadIdx.x;
    if (t >= E0) return;
    int g = ei0[E0 + t];
    int old = atomicAdd(&g_cnt[g], 1);
    if (old < CAP) g_eix[g * CAP + old] = ei0[t];
}

__global__ void fill12B(const int* __restrict__ ei1, const int* __restrict__ ei2) {
    int t = blockIdx.x * blockDim.x + threadIdx.x;
    int g, s;
    if (t < E1)       { g = GB1 + ei1[E1 + t];                 s = ei1[t]; }
    else if (t < E12) { int e = t - E1; g = GB2 + ei2[E2 + e]; s = ei2[e]; }
    else return;
    int old = atomicAdd(&g_cnt[g], 1);
    if (old < CAP) g_eix[g * CAP + old] = s;
}

__global__ void dinv_r(int start, int nn) {
    int i = blockIdx.x * blockDim.x + threadIdx.x;
    if (i < nn) g_dinv[start + i] = rsqrtf((float)g_cnt[start + i] + 1.0f);
}

// ---------------- staged-x gemm (R13 verbatim) ----------------
#define GEMM_COMPUTE(n_)                                                  \
    __syncthreads();                                                      \
    int lane = tid & 31;                                                  \
    int sub = lane & 7, grp = lane >> 3;                                  \
    int lbase = (tid >> 5) * 16 + grp;                                    \
    ull a01[4] = {0, 0, 0, 0}, a23[4] = {0, 0, 0, 0};                     \
    _Pragma("unroll")                                                     \
    for (int g = 0; g < 8; g++) {                                         \
        ulonglong2 w0 = swu[(4 * g + 0) * 8 + sub];                       \
        ulonglong2 w1 = swu[(4 * g + 1) * 8 + sub];                       \
        ulonglong2 w2 = swu[(4 * g + 2) * 8 + sub];                       \
        ulonglong2 w3 = swu[(4 * g + 3) * 8 + sub];                       \
        _Pragma("unroll")                                                 \
        for (int j = 0; j < 4; j++) {                                     \
            float4 xv = sx[(lbase + 4 * j) * 9 + g];                      \
            a01[j] = fma2_(pk2(xv.x, xv.x), w0.x, a01[j]);                \
            a23[j] = fma2_(pk2(xv.x, xv.x), w0.y, a23[j]);                \
            a01[j] = fma2_(pk2(xv.y, xv.y), w1.x, a01[j]);                \
            a23[j] = fma2_(pk2(xv.y, xv.y), w1.y, a23[j]);                \
            a01[j] = fma2_(pk2(xv.z, xv.z), w2.x, a01[j]);                \
            a23[j] = fma2_(pk2(xv.z, xv.z), w2.y, a23[j]);                \
            a01[j] = fma2_(pk2(xv.w, xv.w), w3.x, a01[j]);                \
            a23[j] = fma2_(pk2(xv.w, xv.w), w3.y, a23[j]);                \
        }                                                                 \
    }                                                                     \
    _Pragma("unroll")                                                     \
    for (int j = 0; j < 4; j++) {                                         \
        int node = blockIdx.x * NPB + lbase + 4 * j;                      \
        if (node < n_) {                                                  \
            ulonglong2 r; r.x = a01[j]; r.y = a23[j];                     \
            ((ulonglong2*)Y)[node * 8 + sub] = r;                        \
        }                                                                 \
    }

__global__ void __launch_bounds__(256)
gemm_fc1(const float4* __restrict__ x,
         const float* __restrict__ fc1w, const float* __restrict__ fc1b,
         const float* __restrict__ w, float4* __restrict__ Y, int n)
{
    __shared__ ulonglong2 swu[256];
    __shared__ float4 sx[NPB * 9];
    __shared__ float4 sfw[32];
    __shared__ float4 sfb[8];
    int tid = threadIdx.x;
    swu[tid] = ((const ulonglong2*)w)[tid];
    if (tid < 32) sfw[tid] = ((const float4*)fc1w)[tid];
    if (tid < 8)  sfb[tid] = ((const float4*)fc1b)[tid];
    __syncthreads();
    int ln = tid >> 1;
    int nd = blockIdx.x * NPB + ln;
    int half = (tid & 1) * 4;
    if (nd < n) {
        float4 xin = x[nd];
        #pragma unroll
        for (int i = 0; i < 4; i++) {
            int q = half + i;
            float4 h = sfb[q];
            float4 r0 = sfw[q], r1 = sfw[8 + q], r2 = sfw[16 + q], r3 = sfw[24 + q];
            h.x += xin.x * r0.x + xin.y * r1.x + xin.z * r2.x + xin.w * r3.x;
            h.y += xin.x * r0.y + xin.y * r1.y + xin.z * r2.y + xin.w * r3.y;
            h.z += xin.x * r0.z + xin.y * r1.z + xin.z * r2.z + xin.w * r3.z;
            h.w += xin.x * r0.w + xin.y * r1.w + xin.z * r2.w + xin.w * r3.w;
            sx[ln * 9 + q] = relu4(h);
        }
    }
    GEMM_COMPUTE(n)
}

__global__ void __launch_bounds__(256)
gemm_down(const float4* __restrict__ in, const float* __restrict__ w,
          float4* __restrict__ Y, int n, int hy, int win)
{
    __shared__ ulonglong2 swu[256];
    __shared__ float4 sx[NPB * 9];
    int tid = threadIdx.x;
    swu[tid] = ((const ulonglong2*)w)[tid];
    int ln = tid >> 1;
    int nd = blockIdx.x * NPB + ln;
    int half = (tid & 1) * 4;
    if (nd < n) {
        int ix = nd / hy, iy = nd - ix * hy;
        const float4* src = in + ((2 * ix) * win + 2 * iy) * 8 + half;
        #pragma unroll
        for (int i = 0; i < 4; i++)
            sx[ln * 9 + half + i] = relu4(src[i]);
    }
    GEMM_COMPUTE(n)
}

__global__ void __launch_bounds__(256)
gemm_upadd(const float4* __restrict__ base, const float4* __restrict__ coarse,
           const float* __restrict__ w, float4* __restrict__ Y, int n, int hy)
{
    __shared__ ulonglong2 swu[256];
    __shared__ float4 sx[NPB * 9];
    int tid = threadIdx.x;
    swu[tid] = ((const ulonglong2*)w)[tid];
    int ln = tid >> 1;
    int nd = blockIdx.x * NPB + ln;
    int half = (tid & 1) * 4;
    if (nd < n) {
        int ix = nd / hy, iy = nd - ix * hy;
        int cn = (ix >> 1) * (hy >> 1) + (iy >> 1);
        const float4* bsrc = base + nd * 8 + half;
        const float4* csrc = coarse + cn * 8 + half;
        #pragma unroll
        for (int i = 0; i < 4; i++) {
            float4 xb = relu4(bsrc[i]);
            float4 xc = relu4(csrc[i]);
            sx[ln * 9 + half + i] =
                make_float4(xb.x + xc.x, xb.y + xc.y, xb.z + xc.z, xb.w + xc.w);
        }
    }
    GEMM_COMPUTE(n)
}

// ---------------- gather (R13 core, bucket addressing) ----------------
__device__ __forceinline__ void gather_acc(
    const ulonglong2* __restrict__ Y, int node, int sub, int gbase,
    const float* __restrict__ bias, ull& a01, ull& a23)
{
    int gn = gbase + node;
    float di = g_dinv[gn];
    int deg = g_cnt[gn];
    if (deg > CAP) deg = CAP;
    int beg = gn * CAP;
    int end = beg + deg;
    float4 bb = ((const float4*)bias)[sub];
    float s2 = di * di;
    ulonglong2 y = Y[node * 8 + sub];
    ull s22 = pk2(s2, s2);
    a01 = fma2_(y.x, s22, pk2(bb.x, bb.y));
    a23 = fma2_(y.y, s22, pk2(bb.z, bb.w));
    for (int p = beg; p < end; p++) {
        int s = g_eix[p];
        float nm = g_dinv[gbase + s] * di;
        ulonglong2 v = Y[s * 8 + sub];
        ull nn = pk2(nm, nm);
        a01 = fma2_(v.x, nn, a01);
        a23 = fma2_(v.y, nn, a23);
    }
}

__global__ void gather(const float4* __restrict__ Yf,
                       const float* __restrict__ bias,
                       float4* __restrict__ OUT, int n, int gbase)
{
    int t = blockIdx.x * blockDim.x + threadIdx.x;
    int node = t >> 3, sub = t & 7;
    if (node >= n) return;
    ull a01, a23;
    gather_acc((const ulonglong2*)Yf, node, sub, gbase, bias, a01, a23);
    ulonglong2 r; r.x = a01; r.y = a23;
    ((ulonglong2*)OUT)[node * 8 + sub] = r;
}

__global__ void gather_fc2(const float4* __restrict__ Yf,
                           const float* __restrict__ bias,
                           const float* __restrict__ w2, const float* __restrict__ b2,
                           float* __restrict__ out, int n)
{
    __shared__ float sw[96];
    int tid = threadIdx.x;
    if (tid < 96) sw[tid] = w2[tid];
    __syncthreads();
    int t = blockIdx.x * blockDim.x + tid;
    int node = t >> 3, sub = t & 7;
    if (node >= n) return;
    ull a01, a23;
    gather_acc((const ulonglong2*)Yf, node, sub, 0, bias, a01, a23);
    float2 v01 = up2_(a01), v23 = up2_(a23);
    float4 v = relu4(make_float4(v01.x, v01.y, v23.x, v23.y));
    int c = 4 * sub;
    float p0 = v.x * sw[(c+0)*3+0] + v.y * sw[(c+1)*3+0] + v.z * sw[(c+2)*3+0] + v.w * sw[(c+3)*3+0];
    float p1 = v.x * sw[(c+0)*3+1] + v.y * sw[(c+1)*3+1] + v.z * sw[(c+2)*3+1] + v.w * sw[(c+3)*3+1];
    float p2 = v.x * sw[(c+0)*3+2] + v.y * sw[(c+1)*3+2] + v.z * sw[(c+2)*3+2] + v.w * sw[(c+3)*3+2];
    #pragma unroll
    for (int off = 4; off; off >>= 1) {
        p0 += __shfl_down_sync(0xffffffffu, p0, off, 8);
        p1 += __shfl_down_sync(0xffffffffu, p1, off, 8);
        p2 += __shfl_down_sync(0xffffffffu, p2, off, 8);
    }
    if (sub == 0) {
        out[node * 3 + 0] = p0 + __ldg(&b2[0]);
        out[node * 3 + 1] = p1 + __ldg(&b2[1]);
        out[node * 3 + 2] = p2 + __ldg(&b2[2]);
    }
}

// ---------------------------------------------------------------------------
static inline int ceil_div(int a, int b) { return (a + b - 1) / b; }

static cudaStream_t g_s2 = 0;
static cudaEvent_t  g_evTop = 0, g_evZ = 0, g_evF = 0, g_ev12 = 0;

extern "C" void kernel_launch(void* const* d_in, const int* in_sizes, int n_in,
                              void* d_out, int out_size) {
    const float* x     = (const float*)d_in[0];
    const float* fc1_w = (const float*)d_in[1];
    const float* fc1_b = (const float*)d_in[2];
    const float* w1 = (const float*)d_in[3];  const float* b1 = (const float*)d_in[4];
    const float* w2 = (const float*)d_in[5];  const float* b2 = (const float*)d_in[6];
    const float* w3 = (const float*)d_in[7];  const float* b3 = (const float*)d_in[8];
    const float* w4 = (const float*)d_in[9];  const float* b4 = (const float*)d_in[10];
    const float* w5 = (const float*)d_in[11]; const float* b5 = (const float*)d_in[12];
    const float* fc2_w = (const float*)d_in[13];
    const float* fc2_b = (const float*)d_in[14];
    const int* ei0 = (const int*)d_in[18];
    const int* ei1 = (const int*)d_in[19];
    const int* ei2 = (const int*)d_in[20];
    float* out = (float*)d_out;

    float4 *Y, *H, *G2, *G4, *G3;
    cudaGetSymbolAddress((void**)&Y,  g_Y);
    cudaGetSymbolAddress((void**)&H,  g_H);
    cudaGetSymbolAddress((void**)&G2, g_G2);
    cudaGetSymbolAddress((void**)&G4, g_G4);
    cudaGetSymbolAddress((void**)&G3, g_G3);

    if (!g_s2) {
        cudaStreamCreateWithFlags(&g_s2, cudaStreamNonBlocking);
        cudaEventCreateWithFlags(&g_evTop, cudaEventDisableTiming);
        cudaEventCreateWithFlags(&g_evZ,  cudaEventDisableTiming);
        cudaEventCreateWithFlags(&g_evF,  cudaEventDisableTiming);
        cudaEventCreateWithFlags(&g_ev12, cudaEventDisableTiming);
    }

    const int TB = 256;

    // Fork side stream.
    cudaEventRecord(g_evTop, 0);
    cudaStreamWaitEvent(g_s2, g_evTop, 0);

    // main: zero cursors, level-0 bucket fill, level-0 dinv
    zero_cnt<<<ceil_div(M, TB), TB>>>();
    cudaEventRecord(g_evZ, 0);
    fill0B<<<ceil_div(E0, TB), TB>>>(ei0);
    dinv_r<<<ceil_div(N0, TB), TB>>>(0, N0);

    // side: gemm_fc1 (independent), then level-1/2 fill + dinv
    gemm_fc1<<<ceil_div(N0, NPB), TB, 0, g_s2>>>((const float4*)x, fc1_w, fc1_b,
                                                 w1, Y, N0);
    cudaEventRecord(g_evF, g_s2);
    cudaStreamWaitEvent(g_s2, g_evZ, 0);
    fill12B<<<ceil_div(E12, TB), TB, 0, g_s2>>>(ei1, ei2);
    dinv_r<<<ceil_div(M - N0, TB), TB, 0, g_s2>>>(N0, M - N0);
    cudaEventRecord(g_ev12, g_s2);

    // main: gather1 (needs fill0+dinv0 on main, gemm_fc1 on side)
    cudaStreamWaitEvent(0, g_evF, 0);
    gather<<<N0 / 32, TB>>>(Y, b1, H, N0, 0);

    // join level-1/2 build before level-1 gather
    cudaStreamWaitEvent(0, g_ev12, 0);

    // GCN2
    gemm_down<<<ceil_div(N1, NPB), TB>>>(H, w2, Y, N1, NYg / 2, NYg);
    gather<<<N1 / 32, TB>>>(Y, b2, G2, N1, GB1);

    // GCN3
    gemm_down<<<ceil_div(N2, NPB), TB>>>(G2, w3, Y, N2, NYg / 4, NYg / 2);
    gather<<<N2 / 32, TB>>>(Y, b3, G3, N2, GB2);

    // GCN4
    gemm_upadd<<<ceil_div(N1, NPB), TB>>>(G2, G3, w4, Y, N1, NYg / 2);
    gather<<<N1 / 32, TB>>>(Y, b4, G4, N1, GB1);

    // GCN5 + fc2
    gemm_upadd<<<ceil_div(N0, NPB), TB>>>(H, G4, w5, Y, N0, NYg);
    gather_fc2<<<N0 / 32, TB>>>(Y, b5, fc2_w, fc2_b, out, N0);

    (void)in_sizes; (void)n_in; (void)out_size;
}